// round 8
// baseline (speedup 1.0000x reference)
#include <cuda_runtime.h>
#include <cuda_bf16.h>

// Retrace loss, single fused kernel. (No inline PTX — toolchain-safe.)
// Layout: warp w owns cols [w*128, (w+1)*128).
//   Staging (coalesced, 2-page load batches): lane loads cols w*128+p*32+lane,
//     builds affine maps (A,B) in registers, transposes A,B,Q through a
//     warp-private smem slice (syncwarp only).
//   Scan: lane owns contiguous cols w*128+4*lane..+3; serial compose 4,
//     one 32-lane warp suffix scan, cross-warp combine.
// Completion: two-level atomicInc tree (64 group counters + 1 root) to kill
//   same-address atomic serialization; one __threadfence before arrival
//   (proven-running pattern from R5). Counters wrap -> deterministic replays.

#define S_STRIDE 1025
#define T_LEN    1024
#define NROWS    4096
#define GAMMA_F  0.99f
#define EPS_F    1e-10f
#define NTHREADS 256
#define NGROUPS  64
#define GSIZE    64   // NROWS / NGROUPS

__device__ double   g_part[NROWS];
__device__ unsigned g_cnt1[NGROUPS];  // zero-init; wraps at GSIZE-1
__device__ unsigned g_cnt2;           // zero-init; wraps at NGROUPS-1

struct Aff { float a, b; };

__device__ __forceinline__ Aff comp(Aff f, Aff g) {
    Aff r;
    r.a = fmaf(f.b, g.a, f.a);
    r.b = f.b * g.b;
    return r;
}

__global__ void __launch_bounds__(NTHREADS)
retrace_kernel(const float* __restrict__ Q,
               const float* __restrict__ eQ,
               const float* __restrict__ tQ,
               const float* __restrict__ r,
               const float* __restrict__ tp,
               const float* __restrict__ bp,
               float* __restrict__ out)
{
    __shared__ __align__(16) float sA [8][128];
    __shared__ __align__(16) float sB [8][128];
    __shared__ __align__(16) float sQv[8][128];
    __shared__ float swA[8], swB[8], exA[8], exB[8];
    __shared__ double ssum[8];
    __shared__ bool s_last;

    const int row = blockIdx.x;
    const long base = (long)row * S_STRIDE;
    const int t = threadIdx.x;
    const unsigned lane = t & 31u;
    const unsigned w = t >> 5;
    const int seg = (int)w * 128;

    // ---- staging: 2 pages of loads batched (12 LDG in flight), then compute+store
#pragma unroll
    for (int h = 0; h < 2; h++) {
        float pt[2], pb[2], rv[2], ev[2], tqv[2], qv[2];
        int il[2];
#pragma unroll
        for (int p = 0; p < 2; p++) {
            il[p] = (h * 2 + p) * 32 + (int)lane;            // 0..127 within segment
            const int i  = seg + il[p];
            const int i2 = (i < T_LEN - 1) ? i + 2 : T_LEN;  // clamp; unused if i==1023
            pt[p]  = __ldg(&tp[base + i2]);
            pb[p]  = __ldg(&bp[base + i2]);
            rv[p]  = __ldg(&r [base + i + 1]);
            ev[p]  = __ldg(&eQ[base + i2]);
            tqv[p] = __ldg(&tQ[base + i2]);
            qv[p]  = __ldg(&Q [base + i]);
        }
#pragma unroll
        for (int p = 0; p < 2; p++) {
            const int i = seg + il[p];
            float a, b;
            if (i < T_LEN - 1) {
                const float c = fminf(fmaxf(__fdividef(pt[p], pb[p]), EPS_F), 1.0f);
                b = GAMMA_F * c;
                a = fmaf(GAMMA_F, ev[p], rv[p]) - b * tqv[p];
            } else {                      // i == 1023: identity map
                a = 0.0f; b = 1.0f;
            }
            sA [w][il[p]] = a;
            sB [w][il[p]] = b;
            sQv[w][il[p]] = qv[p];
        }
    }
    const float init = __ldg(&Q[base + T_LEN]);
    __syncwarp();

    // ---- contiguous read-back: lane owns cols seg + 4*lane .. +3
    const float4 a4 = reinterpret_cast<const float4*>(sA [w])[lane];
    const float4 b4 = reinterpret_cast<const float4*>(sB [w])[lane];
    const float4 q4 = reinterpret_cast<const float4*>(sQv[w])[lane];
    Aff loc[4] = { {a4.x, b4.x}, {a4.y, b4.y}, {a4.z, b4.z}, {a4.w, b4.w} };
    const float qv[4] = { q4.x, q4.y, q4.z, q4.w };

    // ---- serial suffix composition within thread
    Aff suf[4];
    suf[3] = loc[3];
#pragma unroll
    for (int k = 2; k >= 0; k--) suf[k] = comp(loc[k], suf[k + 1]);

    // ---- single warp-level inclusive suffix scan of thread aggregates
    Aff v = suf[0];
#pragma unroll
    for (int off = 1; off < 32; off <<= 1) {
        const float oa = __shfl_down_sync(0xffffffffu, v.a, off);
        const float ob = __shfl_down_sync(0xffffffffu, v.b, off);
        if (lane + off < 32) { Aff g; g.a = oa; g.b = ob; v = comp(v, g); }
    }

    // in-warp EXCLUSIVE suffix (threads lane+1..31)
    const float ea = __shfl_down_sync(0xffffffffu, v.a, 1);
    const float eb = __shfl_down_sync(0xffffffffu, v.b, 1);
    Aff inwexcl;
    if (lane == 31) { inwexcl.a = 0.0f; inwexcl.b = 1.0f; }
    else            { inwexcl.a = ea;   inwexcl.b = eb;   }

    // ---- cross-warp exclusive suffix (8 warps)
    if (lane == 0) { swA[w] = v.a; swB[w] = v.b; }
    __syncthreads();
    if (t == 0) {
        Aff acc; acc.a = 0.0f; acc.b = 1.0f;
        for (int ww = 7; ww >= 0; ww--) {
            exA[ww] = acc.a; exB[ww] = acc.b;
            Aff tot; tot.a = swA[ww]; tot.b = swB[ww];
            acc = comp(tot, acc);
        }
    }
    __syncthreads();
    Aff W; W.a = exA[w]; W.b = exB[w];
    const Aff S = comp(inwexcl, W);

    // ---- apply composed maps, accumulate squared error
    float fsum = 0.0f;
#pragma unroll
    for (int k = 0; k < 4; k++) {
        const Aff m = comp(suf[k], S);
        const float y = fmaf(m.b, init, m.a);
        const float d = qv[k] - y;
        fsum = fmaf(d, d, fsum);
    }

    // ---- warp reduction fp32, cross-warp double
#pragma unroll
    for (int off = 16; off > 0; off >>= 1)
        fsum += __shfl_down_sync(0xffffffffu, fsum, off);
    if (lane == 0) ssum[w] = (double)fsum;
    __syncthreads();

    if (t == 0) {
        double x = 0.0;
#pragma unroll
        for (int i = 0; i < 8; i++) x += ssum[i];
        __stcg(&g_part[row], x);      // L2-visible store
        __threadfence();              // release: partial visible before arrival
        bool last = false;
        const unsigned o1 = atomicInc(&g_cnt1[row >> 6], GSIZE - 1);
        if (o1 == GSIZE - 1) {
            const unsigned o2 = atomicInc(&g_cnt2, NGROUPS - 1);
            last = (o2 == NGROUPS - 1);
        }
        s_last = last;
    }
    __syncthreads();

    // ---- very last block reduces all partials and writes output
    if (s_last) {
        double x = 0.0;
        for (int i = t; i < NROWS; i += NTHREADS)
            x += __ldcg(&g_part[i]);
#pragma unroll
        for (int off = 16; off > 0; off >>= 1)
            x += __shfl_down_sync(0xffffffffu, x, off);
        __shared__ double fs2[8];
        if (lane == 0) fs2[w] = x;
        __syncthreads();
        if (t == 0) {
            double tot = 0.0;
#pragma unroll
            for (int i = 0; i < 8; i++) tot += fs2[i];
            out[0] = (float)(tot / (double)((long long)NROWS * T_LEN));
        }
    }
}

extern "C" void kernel_launch(void* const* d_in, const int* in_sizes, int n_in,
                              void* d_out, int out_size)
{
    const float* Q   = (const float*)d_in[0];
    const float* eQ  = (const float*)d_in[1];
    const float* tQ  = (const float*)d_in[2];
    const float* r   = (const float*)d_in[3];
    const float* tp  = (const float*)d_in[4];
    const float* bp  = (const float*)d_in[5];
    float* out = (float*)d_out;

    retrace_kernel<<<NROWS, NTHREADS>>>(Q, eQ, tQ, r, tp, bp, out);
}

// round 10
// speedup vs baseline: 1.2640x; 1.2640x over previous
#include <cuda_runtime.h>
#include <cuda_bf16.h>

// Retrace loss — persistent-CTA, software-pipelined kernel.
// grid = 592 = 148 SM * 4 CTA; each CTA grid-strides over rows (6-7 rows).
// Per row iteration:
//   1. build affine maps from regs loaded LAST iteration, STS to warp-private slice
//   2. issue next row's 25 global loads (fly during this row's scan)
//   3. LDS float4, serial compose 4, one warp suffix scan, cross-warp combine
//   4. epilogue -> per-thread double accumulator
// Completion: ONE arrival per CTA (592 total), last CTA reduces 592 partials.
// Affine composition: (A1,B1) o (A2,B2) = (A1 + B1*A2, B1*B2).

#define S_STRIDE 1025
#define T_LEN    1024
#define NROWS    4096
#define GAMMA_F  0.99f
#define EPS_F    1e-10f
#define NTHREADS 256
#define GRID     592

__device__ double   g_part[GRID];
__device__ unsigned g_cnt = 0;   // wraps at GRID-1 -> deterministic across replays

struct Aff { float a, b; };

__device__ __forceinline__ Aff comp(Aff f, Aff g) {
    Aff r;
    r.a = fmaf(f.b, g.a, f.a);
    r.b = f.b * g.b;
    return r;
}

struct RowRegs {
    float pt[4], pb[4], rv[4], ev[4], tq[4], qv[4];
    float init;
};

__device__ __forceinline__ void load_row(RowRegs& R, long base, int seg, int lane,
                                         const float* __restrict__ Q,
                                         const float* __restrict__ eQ,
                                         const float* __restrict__ tQ,
                                         const float* __restrict__ r,
                                         const float* __restrict__ tp,
                                         const float* __restrict__ bp)
{
#pragma unroll
    for (int p = 0; p < 4; p++) {
        const int i  = seg + p * 32 + lane;               // global col, 0..1023
        const int i2 = (i < T_LEN - 1) ? i + 2 : T_LEN;   // clamp; unused if i==1023
        R.pt[p] = __ldg(&tp[base + i2]);
        R.pb[p] = __ldg(&bp[base + i2]);
        R.rv[p] = __ldg(&r [base + i + 1]);
        R.ev[p] = __ldg(&eQ[base + i2]);
        R.tq[p] = __ldg(&tQ[base + i2]);
        R.qv[p] = __ldg(&Q [base + i]);
    }
    R.init = __ldg(&Q[base + T_LEN]);
}

__global__ void __launch_bounds__(NTHREADS, 4)
retrace_kernel(const float* __restrict__ Q,
               const float* __restrict__ eQ,
               const float* __restrict__ tQ,
               const float* __restrict__ r,
               const float* __restrict__ tp,
               const float* __restrict__ bp,
               float* __restrict__ out)
{
    __shared__ __align__(16) float sA [8][128];
    __shared__ __align__(16) float sB [8][128];
    __shared__ __align__(16) float sQv[8][128];
    __shared__ float swA[8], swB[8], exA[8], exB[8];
    __shared__ double ssum[8];
    __shared__ bool s_last;

    const int bid = blockIdx.x;
    const int t = threadIdx.x;
    const int lane = t & 31;
    const unsigned w = t >> 5;
    const int seg = (int)w * 128;

    double acc = 0.0;       // per-thread squared-error accumulator across rows
    RowRegs R;

    int row = bid;
    load_row(R, (long)row * S_STRIDE, seg, lane, Q, eQ, tQ, r, tp, bp);

    while (row < NROWS) {
        const int next = row + GRID;

        // ---- 1. build maps for current row from in-register loads, stage to smem
        float a_[4], b_[4], q_[4];
#pragma unroll
        for (int p = 0; p < 4; p++) {
            const int i = seg + p * 32 + lane;
            if (i < T_LEN - 1) {
                const float c = fminf(fmaxf(__fdividef(R.pt[p], R.pb[p]), EPS_F), 1.0f);
                b_[p] = GAMMA_F * c;
                a_[p] = fmaf(GAMMA_F, R.ev[p], R.rv[p]) - b_[p] * R.tq[p];
            } else {               // i == 1023: identity map
                a_[p] = 0.0f; b_[p] = 1.0f;
            }
            q_[p] = R.qv[p];
        }
        const float init = R.init;

        __syncwarp();              // prior iteration's LDS of this slice is done
#pragma unroll
        for (int p = 0; p < 4; p++) {
            const int il = p * 32 + lane;
            sA [w][il] = a_[p];
            sB [w][il] = b_[p];
            sQv[w][il] = q_[p];
        }
        __syncwarp();

        // ---- 2. issue next row's loads now; they fly during the scan below
        if (next < NROWS)
            load_row(R, (long)next * S_STRIDE, seg, lane, Q, eQ, tQ, r, tp, bp);

        // ---- 3. contiguous read-back: lane owns cols seg + 4*lane .. +3
        const float4 a4 = reinterpret_cast<const float4*>(sA [w])[lane];
        const float4 b4 = reinterpret_cast<const float4*>(sB [w])[lane];
        const float4 q4 = reinterpret_cast<const float4*>(sQv[w])[lane];
        Aff loc[4] = { {a4.x, b4.x}, {a4.y, b4.y}, {a4.z, b4.z}, {a4.w, b4.w} };
        const float qv[4] = { q4.x, q4.y, q4.z, q4.w };

        // serial suffix composition within thread
        Aff suf[4];
        suf[3] = loc[3];
#pragma unroll
        for (int k = 2; k >= 0; k--) suf[k] = comp(loc[k], suf[k + 1]);

        // single warp-level inclusive suffix scan of thread aggregates
        Aff v = suf[0];
#pragma unroll
        for (int off = 1; off < 32; off <<= 1) {
            const float oa = __shfl_down_sync(0xffffffffu, v.a, off);
            const float ob = __shfl_down_sync(0xffffffffu, v.b, off);
            if (lane + off < 32) { Aff g; g.a = oa; g.b = ob; v = comp(v, g); }
        }

        // in-warp EXCLUSIVE suffix (threads lane+1..31)
        const float ea = __shfl_down_sync(0xffffffffu, v.a, 1);
        const float eb = __shfl_down_sync(0xffffffffu, v.b, 1);
        Aff inwexcl;
        if (lane == 31) { inwexcl.a = 0.0f; inwexcl.b = 1.0f; }
        else            { inwexcl.a = ea;   inwexcl.b = eb;   }

        // cross-warp exclusive suffix (8 warps)
        if (lane == 0) { swA[w] = v.a; swB[w] = v.b; }
        __syncthreads();
        if (t == 0) {
            Aff c2; c2.a = 0.0f; c2.b = 1.0f;
            for (int ww = 7; ww >= 0; ww--) {
                exA[ww] = c2.a; exB[ww] = c2.b;
                Aff tot; tot.a = swA[ww]; tot.b = swB[ww];
                c2 = comp(tot, c2);
            }
        }
        __syncthreads();
        Aff W; W.a = exA[w]; W.b = exB[w];
        const Aff S = comp(inwexcl, W);

        // ---- 4. epilogue: apply composed maps, accumulate squared error
        float fsum = 0.0f;
#pragma unroll
        for (int k = 0; k < 4; k++) {
            const Aff m = comp(suf[k], S);
            const float y = fmaf(m.b, init, m.a);
            const float d = qv[k] - y;
            fsum = fmaf(d, d, fsum);
        }
        acc += (double)fsum;

        row = next;
    }

    // ---- final: block-reduce per-thread doubles, one arrival per CTA
#pragma unroll
    for (int off = 16; off > 0; off >>= 1)
        acc += __shfl_down_sync(0xffffffffu, acc, off);
    if (lane == 0) ssum[w] = acc;
    __syncthreads();

    if (t == 0) {
        double x = 0.0;
#pragma unroll
        for (int i = 0; i < 8; i++) x += ssum[i];
        __stcg(&g_part[bid], x);
        __threadfence();
        const unsigned old = atomicInc(&g_cnt, GRID - 1);  // wraps after GRID arrivals
        s_last = (old == GRID - 1);
    }
    __syncthreads();

    // ---- very last CTA reduces all partials and writes output
    if (s_last) {
        double x = 0.0;
        for (int i = t; i < GRID; i += NTHREADS)
            x += __ldcg(&g_part[i]);
#pragma unroll
        for (int off = 16; off > 0; off >>= 1)
            x += __shfl_down_sync(0xffffffffu, x, off);
        __shared__ double fs2[8];
        if (lane == 0) fs2[w] = x;
        __syncthreads();
        if (t == 0) {
            double tot = 0.0;
#pragma unroll
            for (int i = 0; i < 8; i++) tot += fs2[i];
            out[0] = (float)(tot / (double)((long long)NROWS * T_LEN));
        }
    }
}

extern "C" void kernel_launch(void* const* d_in, const int* in_sizes, int n_in,
                              void* d_out, int out_size)
{
    const float* Q   = (const float*)d_in[0];
    const float* eQ  = (const float*)d_in[1];
    const float* tQ  = (const float*)d_in[2];
    const float* r   = (const float*)d_in[3];
    const float* tp  = (const float*)d_in[4];
    const float* bp  = (const float*)d_in[5];
    float* out = (float*)d_out;

    retrace_kernel<<<GRID, NTHREADS>>>(Q, eQ, tQ, r, tp, bp, out);
}